// round 2
// baseline (speedup 1.0000x reference)
#include <cuda_runtime.h>
#include <cuda_bf16.h>
#include <cstdint>
#include <cstring>

// Problem: out = x @ kernel[2]   (softmax over length-1 axis == identity)
// x: [8192,1024] f32, kernel: [3,1024,1024] f32, out: [8192,1024] f32
#define BROWS 8192
#define DDIM  1024

// Static device scratch (allocation-free per harness rules)
__device__ __nv_bfloat16 g_xhi[BROWS * DDIM];
__device__ __nv_bfloat16 g_xlo[BROWS * DDIM];
__device__ __nv_bfloat16 g_whi[DDIM * DDIM];
__device__ __nv_bfloat16 g_wlo[DDIM * DDIM];

static __device__ __forceinline__ unsigned short bf_as_us(__nv_bfloat16 b) {
    unsigned short u;
    memcpy(&u, &b, 2);
    return u;
}

// fp32 -> bf16 hi/lo split, float4 vectorized. which: 0 -> x arrays, 1 -> w arrays
__global__ void split_convert_kernel(const float4* __restrict__ src, int n4, int which) {
    int i = blockIdx.x * blockDim.x + threadIdx.x;
    if (i >= n4) return;
    float4 v = src[i];
    float vv[4] = {v.x, v.y, v.z, v.w};
    unsigned short h[4], l[4];
#pragma unroll
    for (int j = 0; j < 4; j++) {
        __nv_bfloat16 hb = __float2bfloat16(vv[j]);
        float rem = vv[j] - __bfloat162float(hb);
        __nv_bfloat16 lb = __float2bfloat16(rem);
        h[j] = bf_as_us(hb);
        l[j] = bf_as_us(lb);
    }
    uint2 hv = make_uint2((uint32_t)h[0] | ((uint32_t)h[1] << 16),
                          (uint32_t)h[2] | ((uint32_t)h[3] << 16));
    uint2 lv = make_uint2((uint32_t)l[0] | ((uint32_t)l[1] << 16),
                          (uint32_t)l[2] | ((uint32_t)l[3] << 16));
    uint2* hd = which ? (uint2*)g_whi : (uint2*)g_xhi;
    uint2* ld = which ? (uint2*)g_wlo : (uint2*)g_xlo;
    hd[i] = hv;
    ld[i] = lv;
}

// ---------------- GEMM: bf16x3 split-precision, mma.sync.m16n8k16 ----------------
// BM=128, BN=128, BK=64, 256 threads = 8 warps (4 x 2), warp tile 32x64.
// smem per stage: A_hi 16K | A_lo 16K | B_hi 16K | B_lo 16K = 64K, 2 stages = 128K dyn.

#define STAGE_BYTES 65536
#define A_LO_OFF    16384
#define B_HI_OFF    32768
#define B_LO_OFF    49152

static __device__ __forceinline__ void cpa16(uint32_t saddr, const void* gptr) {
    asm volatile("cp.async.cg.shared.global [%0], [%1], 16;\n" :: "r"(saddr), "l"(gptr));
}
static __device__ __forceinline__ void cp_commit() {
    asm volatile("cp.async.commit_group;\n" ::: "memory");
}
static __device__ __forceinline__ void cp_wait_all() {
    asm volatile("cp.async.wait_group 0;\n" ::: "memory");
}
static __device__ __forceinline__ void ldsm4(uint32_t* r, uint32_t a) {
    asm volatile("ldmatrix.sync.aligned.m8n8.x4.shared.b16 {%0,%1,%2,%3}, [%4];"
                 : "=r"(r[0]), "=r"(r[1]), "=r"(r[2]), "=r"(r[3]) : "r"(a));
}
static __device__ __forceinline__ void ldsm4t(uint32_t* r, uint32_t a) {
    asm volatile("ldmatrix.sync.aligned.m8n8.x4.trans.shared.b16 {%0,%1,%2,%3}, [%4];"
                 : "=r"(r[0]), "=r"(r[1]), "=r"(r[2]), "=r"(r[3]) : "r"(a));
}
static __device__ __forceinline__ void mma16816(float* c, const uint32_t* a, const uint32_t* b) {
    asm volatile(
        "mma.sync.aligned.m16n8k16.row.col.f32.bf16.bf16.f32 "
        "{%0,%1,%2,%3}, {%4,%5,%6,%7}, {%8,%9}, {%0,%1,%2,%3};"
        : "+f"(c[0]), "+f"(c[1]), "+f"(c[2]), "+f"(c[3])
        : "r"(a[0]), "r"(a[1]), "r"(a[2]), "r"(a[3]), "r"(b[0]), "r"(b[1]));
}

__global__ void __launch_bounds__(256, 1) gemm_bf16x3_kernel(float* __restrict__ out) {
    extern __shared__ char smem[];
    const int tid    = threadIdx.x;
    const int lane   = tid & 31;
    const int wid    = tid >> 5;
    const int warp_m = wid >> 1;  // 0..3
    const int warp_n = wid & 1;   // 0..1
    const int cta_m  = blockIdx.y * 128;
    const int cta_n  = blockIdx.x * 128;

    const __nv_bfloat16* __restrict__ Ahi = g_xhi;
    const __nv_bfloat16* __restrict__ Alo = g_xlo;
    const __nv_bfloat16* __restrict__ Bhi = g_whi;
    const __nv_bfloat16* __restrict__ Blo = g_wlo;

    uint32_t sbase = (uint32_t)__cvta_generic_to_shared(smem);

    float c[2][8][4];
#pragma unroll
    for (int i = 0; i < 2; i++)
#pragma unroll
        for (int j = 0; j < 8; j++)
#pragma unroll
            for (int k = 0; k < 4; k++) c[i][j][k] = 0.0f;

    // tile loader: kt = K-tile index (BK=64), s = stage
    auto load_stage = [&](int kt, int s) {
        uint32_t st = sbase + s * STAGE_BYTES;
        // A: 128 rows x 8 chunks (16B each)
#pragma unroll
        for (int i = 0; i < 4; i++) {
            int chunk = tid + i * 256;
            int r = chunk >> 3, cc = chunk & 7;
            long goff = (long)(cta_m + r) * DDIM + kt * 64 + cc * 8;
            uint32_t sa = st + r * 128 + ((cc ^ (r & 7)) * 16);
            cpa16(sa, Ahi + goff);
            cpa16(sa + A_LO_OFF, Alo + goff);
        }
        // B: 64 rows(k) x 16 chunks
#pragma unroll
        for (int i = 0; i < 4; i++) {
            int chunk = tid + i * 256;
            int k = chunk >> 4, cc = chunk & 15;
            long goff = (long)(kt * 64 + k) * DDIM + cta_n + cc * 8;
            uint32_t sb = st + B_HI_OFF + k * 256 + ((cc ^ (k & 7)) * 16);
            cpa16(sb, Bhi + goff);
            cpa16(sb + 16384, Blo + goff);
        }
    };

    load_stage(0, 0);
    cp_commit();

    const int KT = DDIM / 64;  // 16
    for (int kt = 0; kt < KT; kt++) {
        cp_wait_all();
        __syncthreads();
        if (kt + 1 < KT) {
            load_stage(kt + 1, (kt + 1) & 1);
            cp_commit();
        }
        uint32_t st = sbase + (kt & 1) * STAGE_BYTES;

#pragma unroll
        for (int kk = 0; kk < 4; kk++) {
            uint32_t a_hi[2][4], a_lo[2][4];
            uint32_t b_hi[4][4], b_lo[4][4];  // [n16-group][4 regs = two n8 frags]

#pragma unroll
            for (int mt = 0; mt < 2; mt++) {
                int row = warp_m * 32 + mt * 16 + (lane & 15);
                int chunk = kk * 2 + (lane >> 4);
                uint32_t addr = st + row * 128 + ((chunk ^ (row & 7)) * 16);
                ldsm4(a_hi[mt], addr);
                ldsm4(a_lo[mt], addr + A_LO_OFF);
            }
#pragma unroll
            for (int nt = 0; nt < 4; nt++) {
                int k = kk * 16 + (lane & 15);
                int nchunk = warp_n * 8 + nt * 2 + (lane >> 4);
                uint32_t addr = st + B_HI_OFF + k * 256 + ((nchunk ^ (k & 7)) * 16);
                ldsm4t(b_hi[nt], addr);
                ldsm4t(b_lo[nt], addr + 16384);
            }
#pragma unroll
            for (int mt = 0; mt < 2; mt++) {
#pragma unroll
                for (int nj = 0; nj < 8; nj++) {
                    const uint32_t* bh = &b_hi[nj >> 1][(nj & 1) * 2];
                    const uint32_t* bl = &b_lo[nj >> 1][(nj & 1) * 2];
                    mma16816(c[mt][nj], a_hi[mt], bh);  // hi*hi
                    mma16816(c[mt][nj], a_hi[mt], bl);  // hi*lo
                    mma16816(c[mt][nj], a_lo[mt], bh);  // lo*hi
                }
            }
        }
    }

    // Epilogue: fragment rows gr=lane/4 (+8), cols (lane%4)*2 (+1)
#pragma unroll
    for (int mt = 0; mt < 2; mt++) {
#pragma unroll
        for (int nj = 0; nj < 8; nj++) {
            int row = cta_m + warp_m * 32 + mt * 16 + (lane >> 2);
            int col = cta_n + warp_n * 64 + nj * 8 + (lane & 3) * 2;
            float2 v0 = make_float2(c[mt][nj][0], c[mt][nj][1]);
            float2 v1 = make_float2(c[mt][nj][2], c[mt][nj][3]);
            *reinterpret_cast<float2*>(&out[(long)row * DDIM + col]) = v0;
            *reinterpret_cast<float2*>(&out[(long)(row + 8) * DDIM + col]) = v1;
        }
    }
}

extern "C" void kernel_launch(void* const* d_in, const int* in_sizes, int n_in,
                              void* d_out, int out_size) {
    const float* x = (const float*)d_in[0];                       // [8192,1024]
    const float* kern = (const float*)d_in[1];                    // [3,1024,1024]
    const float* wv = kern + 2L * DDIM * DDIM;                    // kernel[2]
    float* out = (float*)d_out;

    // Split x and w_v into bf16 hi/lo
    split_convert_kernel<<<(BROWS * DDIM / 4 + 255) / 256, 256>>>(
        (const float4*)x, BROWS * DDIM / 4, 0);
    split_convert_kernel<<<(DDIM * DDIM / 4 + 255) / 256, 256>>>(
        (const float4*)wv, DDIM * DDIM / 4, 1);

    // GEMM
    cudaFuncSetAttribute(gemm_bf16x3_kernel,
                         cudaFuncAttributeMaxDynamicSharedMemorySize, 2 * STAGE_BYTES);
    dim3 grid(DDIM / 128, BROWS / 128);  // (8, 64)
    gemm_bf16x3_kernel<<<grid, 256, 2 * STAGE_BYTES>>>(out);
}

// round 4
// speedup vs baseline: 2.3640x; 2.3640x over previous
#include <cuda_runtime.h>
#include <cuda_fp16.h>
#include <cstdint>

// out = x @ kernel[2]  (seq_len==1 -> softmax over length-1 axis is identity)
// x: [8192,1024] f32, kernel: [3,1024,1024] f32, out: [8192,1024] f32
#define BROWS 8192
#define DDIM  1024

// Static device scratch (allocation-free rules)
__device__ __half g_xh[BROWS * DDIM];   // 16 MB
__device__ __half g_wh[DDIM * DDIM];    // 2 MB, stays [K,N] row-major

// ------------------------- PTX helpers -------------------------
static __device__ __forceinline__ uint32_t smem_u32(const void* p) {
    uint32_t a;
    asm("{ .reg .u64 t; cvta.to.shared.u64 t, %1; cvt.u32.u64 %0, t; }" : "=r"(a) : "l"(p));
    return a;
}
static __device__ __forceinline__ void cpa16(uint32_t saddr, const void* gptr) {
    asm volatile("cp.async.cg.shared.global [%0], [%1], 16;" :: "r"(saddr), "l"(gptr));
}
static __device__ __forceinline__ void cp_commit() {
    asm volatile("cp.async.commit_group;" ::: "memory");
}
static __device__ __forceinline__ void cp_wait2() {
    asm volatile("cp.async.wait_group 2;" ::: "memory");
}
static __device__ __forceinline__ void cp_wait1() {
    asm volatile("cp.async.wait_group 1;" ::: "memory");
}
static __device__ __forceinline__ void cp_wait0() {
    asm volatile("cp.async.wait_group 0;" ::: "memory");
}
static __device__ __forceinline__ void ldsm4(uint32_t* r, uint32_t a) {
    asm volatile("ldmatrix.sync.aligned.m8n8.x4.shared.b16 {%0,%1,%2,%3}, [%4];"
                 : "=r"(r[0]), "=r"(r[1]), "=r"(r[2]), "=r"(r[3]) : "r"(a));
}
static __device__ __forceinline__ void ldsm4t(uint32_t* r, uint32_t a) {
    asm volatile("ldmatrix.sync.aligned.m8n8.x4.trans.shared.b16 {%0,%1,%2,%3}, [%4];"
                 : "=r"(r[0]), "=r"(r[1]), "=r"(r[2]), "=r"(r[3]) : "r"(a));
}
static __device__ __forceinline__ void mma16816(float* c, const uint32_t* a, const uint32_t* b) {
    asm volatile(
        "mma.sync.aligned.m16n8k16.row.col.f32.f16.f16.f32 "
        "{%0,%1,%2,%3}, {%4,%5,%6,%7}, {%8,%9}, {%0,%1,%2,%3};"
        : "+f"(c[0]), "+f"(c[1]), "+f"(c[2]), "+f"(c[3])
        : "r"(a[0]), "r"(a[1]), "r"(a[2]), "r"(a[3]), "r"(b[0]), "r"(b[1]));
}

// ------------------------- convert kernel -------------------------
// Casts x (nx4 float4s) into g_xh and kernel[2] (nw4 float4s) into g_wh.
__global__ void cvt_kernel(const float4* __restrict__ x, const float4* __restrict__ w,
                           int nx4, int nw4) {
    int i = blockIdx.x * blockDim.x + threadIdx.x;
    const float4* src;
    uint2* dst;
    int j;
    if (i < nx4) {
        src = x; dst = (uint2*)g_xh; j = i;
    } else if (i < nx4 + nw4) {
        src = w; dst = (uint2*)g_wh; j = i - nx4;
    } else {
        return;
    }
    float4 v = src[j];
    __half h0 = __float2half_rn(v.x), h1 = __float2half_rn(v.y);
    __half h2 = __float2half_rn(v.z), h3 = __float2half_rn(v.w);
    uint32_t lo = (uint32_t)__half_as_ushort(h0) | ((uint32_t)__half_as_ushort(h1) << 16);
    uint32_t hi = (uint32_t)__half_as_ushort(h2) | ((uint32_t)__half_as_ushort(h3) << 16);
    dst[j] = make_uint2(lo, hi);
}

// ------------------------- GEMM -------------------------
// BM=128, BN=256, BK=64, 4 stages. 256 threads = 8 warps (2 x 4), warp tile 64x64.
// Stage: A 16KB [128 rows x 128B swizzled] | B 32KB [64 k-rows x 512B swizzled].
#define ST_B_OFF    16384
#define STAGE_BYTES 49152
#define N_STAGES    4
#define GEMM_SMEM   (N_STAGES * STAGE_BYTES)   // 196608

__global__ void __launch_bounds__(256, 1) gemm_fp16_kernel(float* __restrict__ out) {
    extern __shared__ char smem[];
    const uint32_t sb = smem_u32(smem);
    const int tid    = threadIdx.x;
    const int lane   = tid & 31;
    const int wid    = tid >> 5;
    const int warp_m = wid >> 2;   // 0..1
    const int warp_n = wid & 3;    // 0..3
    const int cta_m  = blockIdx.y * 128;
    const int cta_n  = blockIdx.x * 256;

    auto load_st = [&](int kt, int s) {
        uint32_t st = sb + s * STAGE_BYTES;
        // A: 128 rows x 8 chunks of 16B
#pragma unroll
        for (int i = 0; i < 4; i++) {
            int ch = tid + i * 256;
            int r = ch >> 3, c = ch & 7;
            size_t g = (size_t)(cta_m + r) * DDIM + kt * 64 + c * 8;
            cpa16(st + r * 128 + ((c ^ (r & 7)) * 16), g_xh + g);
        }
        // B: 64 k-rows x 32 chunks of 16B
#pragma unroll
        for (int i = 0; i < 8; i++) {
            int ch = tid + i * 256;
            int k = ch >> 5, c = ch & 31;
            size_t g = (size_t)(kt * 64 + k) * DDIM + cta_n + c * 8;
            cpa16(st + ST_B_OFF + k * 512 + ((c ^ (k & 7)) * 16), g_wh + g);
        }
    };

    float c[4][8][4];
#pragma unroll
    for (int i = 0; i < 4; i++)
#pragma unroll
        for (int j = 0; j < 8; j++)
#pragma unroll
            for (int q = 0; q < 4; q++) c[i][j][q] = 0.0f;

    load_st(0, 0); cp_commit();
    load_st(1, 1); cp_commit();
    load_st(2, 2); cp_commit();

    for (int kt = 0; kt < 16; kt++) {
        // Outstanding groups entering here: {kt .. min(kt+2,15)}; make kt's data visible.
        if (kt < 14)      cp_wait2();
        else if (kt == 14) cp_wait1();
        else               cp_wait0();
        __syncthreads();
        if (kt + 3 < 16) {
            load_st(kt + 3, (kt + 3) & 3);
            cp_commit();
        }

        uint32_t st = sb + (kt & 3) * STAGE_BYTES;
#pragma unroll
        for (int kk = 0; kk < 4; kk++) {
            uint32_t a[4][4], b[4][4];
#pragma unroll
            for (int mt = 0; mt < 4; mt++) {
                int row = warp_m * 64 + mt * 16 + (lane & 15);
                int ch  = kk * 2 + (lane >> 4);
                ldsm4(a[mt], st + row * 128 + ((ch ^ (row & 7)) * 16));
            }
#pragma unroll
            for (int nt = 0; nt < 4; nt++) {
                int k  = kk * 16 + (lane & 15);
                int nc = warp_n * 8 + nt * 2 + (lane >> 4);
                ldsm4t(b[nt], st + ST_B_OFF + k * 512 + ((nc ^ (k & 7)) * 16));
            }
#pragma unroll
            for (int mt = 0; mt < 4; mt++)
#pragma unroll
                for (int nj = 0; nj < 8; nj++)
                    mma16816(c[mt][nj], a[mt], &b[nj >> 1][(nj & 1) * 2]);
        }
    }

    // Epilogue: direct f32 stores from fragments
#pragma unroll
    for (int mt = 0; mt < 4; mt++) {
#pragma unroll
        for (int nj = 0; nj < 8; nj++) {
            int row = cta_m + warp_m * 64 + mt * 16 + (lane >> 2);
            int col = cta_n + warp_n * 64 + nj * 8 + (lane & 3) * 2;
            *reinterpret_cast<float2*>(&out[(size_t)row * DDIM + col]) =
                make_float2(c[mt][nj][0], c[mt][nj][1]);
            *reinterpret_cast<float2*>(&out[(size_t)(row + 8) * DDIM + col]) =
                make_float2(c[mt][nj][2], c[mt][nj][3]);
        }
    }
}

// ------------------------- launch -------------------------
extern "C" void kernel_launch(void* const* d_in, const int* in_sizes, int n_in,
                              void* d_out, int out_size) {
    const float* x = (const float*)d_in[0];                 // [8192,1024]
    const float* kern = (const float*)d_in[1];              // [3,1024,1024]
    const float* wv = kern + 2L * DDIM * DDIM;              // kernel[2]: [K=1024, N=1024]
    float* out = (float*)d_out;

    const int nx4 = BROWS * DDIM / 4;   // 2,097,152
    const int nw4 = DDIM * DDIM / 4;    // 262,144
    cvt_kernel<<<(nx4 + nw4 + 255) / 256, 256>>>((const float4*)x, (const float4*)wv, nx4, nw4);

    cudaFuncSetAttribute(gemm_fp16_kernel,
                         cudaFuncAttributeMaxDynamicSharedMemorySize, GEMM_SMEM);
    dim3 grid(DDIM / 256, BROWS / 128);  // (4, 64) = 256 CTAs
    gemm_fp16_kernel<<<grid, 256, GEMM_SMEM>>>(out);
}

// round 5
// speedup vs baseline: 2.4264x; 1.0264x over previous
#include <cuda_runtime.h>
#include <cuda_fp16.h>
#include <cstdint>

// out = x @ kernel[2]  (seq_len==1 -> softmax over length-1 axis is identity)
// x: [8192,1024] f32, kernel: [3,1024,1024] f32, out: [8192,1024] f32
#define BROWS 8192
#define DDIM  1024

__device__ __half g_xh[BROWS * DDIM];   // 16 MB
__device__ __half g_wh[DDIM * DDIM];    // 2 MB, [K,N] row-major

// ------------------------- PTX helpers -------------------------
static __device__ __forceinline__ uint32_t smem_u32(const void* p) {
    uint32_t a;
    asm("{ .reg .u64 t; cvta.to.shared.u64 t, %1; cvt.u32.u64 %0, t; }" : "=r"(a) : "l"(p));
    return a;
}
static __device__ __forceinline__ void cpa16(uint32_t saddr, const void* gptr) {
    asm volatile("cp.async.cg.shared.global [%0], [%1], 16;" :: "r"(saddr), "l"(gptr));
}
static __device__ __forceinline__ void cp_commit() {
    asm volatile("cp.async.commit_group;" ::: "memory");
}
static __device__ __forceinline__ void cp_wait2() {
    asm volatile("cp.async.wait_group 2;" ::: "memory");
}
static __device__ __forceinline__ void cp_wait1() {
    asm volatile("cp.async.wait_group 1;" ::: "memory");
}
static __device__ __forceinline__ void cp_wait0() {
    asm volatile("cp.async.wait_group 0;" ::: "memory");
}
static __device__ __forceinline__ void ldsm4(uint32_t* r, uint32_t a) {
    asm volatile("ldmatrix.sync.aligned.m8n8.x4.shared.b16 {%0,%1,%2,%3}, [%4];"
                 : "=r"(r[0]), "=r"(r[1]), "=r"(r[2]), "=r"(r[3]) : "r"(a));
}
static __device__ __forceinline__ void ldsm4t(uint32_t* r, uint32_t a) {
    asm volatile("ldmatrix.sync.aligned.m8n8.x4.trans.shared.b16 {%0,%1,%2,%3}, [%4];"
                 : "=r"(r[0]), "=r"(r[1]), "=r"(r[2]), "=r"(r[3]) : "r"(a));
}
static __device__ __forceinline__ void mma16816(float* c, const uint32_t* a, const uint32_t* b) {
    asm volatile(
        "mma.sync.aligned.m16n8k16.row.col.f32.f16.f16.f32 "
        "{%0,%1,%2,%3}, {%4,%5,%6,%7}, {%8,%9}, {%0,%1,%2,%3};"
        : "+f"(c[0]), "+f"(c[1]), "+f"(c[2]), "+f"(c[3])
        : "r"(a[0]), "r"(a[1]), "r"(a[2]), "r"(a[3]), "r"(b[0]), "r"(b[1]));
}

// ------------------------- convert kernel -------------------------
// 4 coalesced float4 per thread (MLP=4). Grid sized exactly: blocks 0..2047 do x,
// 2048..2303 do w (nx4 divisible by 1024, no mixed blocks).
__global__ void __launch_bounds__(256) cvt_kernel(const float4* __restrict__ x,
                                                  const float4* __restrict__ w,
                                                  int nx4) {
    int base = blockIdx.x * 1024 + threadIdx.x;
    const float4* src;
    uint2* dst;
    if (base < nx4) {
        src = x;
        dst = (uint2*)g_xh;
    } else {
        src = w - nx4;
        dst = ((uint2*)g_wh) - nx4;
    }
    float4 v[4];
#pragma unroll
    for (int j = 0; j < 4; j++) v[j] = src[base + j * 256];
#pragma unroll
    for (int j = 0; j < 4; j++) {
        __half h0 = __float2half_rn(v[j].x), h1 = __float2half_rn(v[j].y);
        __half h2 = __float2half_rn(v[j].z), h3 = __float2half_rn(v[j].w);
        uint32_t lo = (uint32_t)__half_as_ushort(h0) | ((uint32_t)__half_as_ushort(h1) << 16);
        uint32_t hi = (uint32_t)__half_as_ushort(h2) | ((uint32_t)__half_as_ushort(h3) << 16);
        dst[base + j * 256] = make_uint2(lo, hi);
    }
}

// ------------------------- GEMM -------------------------
// BM=128, BN=256, BK=64, 4 stages. 512 threads = 16 warps (4 x 4), warp tile 32x64.
// Stage: A 16KB [128 rows x 128B swizzled] | B 32KB [64 k-rows x 512B swizzled].
#define ST_B_OFF    16384
#define STAGE_BYTES 49152
#define N_STAGES    4
#define GEMM_SMEM   (N_STAGES * STAGE_BYTES)   // 196608

__global__ void __launch_bounds__(512, 1) gemm_fp16_kernel(float* __restrict__ out) {
    extern __shared__ char smem[];
    const uint32_t sb = smem_u32(smem);
    const int tid    = threadIdx.x;
    const int lane   = tid & 31;
    const int wid    = tid >> 5;
    const int warp_m = wid >> 2;   // 0..3 -> m offset *32
    const int warp_n = wid & 3;    // 0..3 -> n offset *64
    const int cta_m  = blockIdx.y * 128;
    const int cta_n  = blockIdx.x * 256;

    auto load_st = [&](int kt, int s) {
        uint32_t st = sb + s * STAGE_BYTES;
        // A: 128 rows x 8 chunks of 16B = 1024 chunks, 2/thread
#pragma unroll
        for (int i = 0; i < 2; i++) {
            int ch = tid + i * 512;
            int r = ch >> 3, c = ch & 7;
            size_t g = (size_t)(cta_m + r) * DDIM + kt * 64 + c * 8;
            cpa16(st + r * 128 + ((c ^ (r & 7)) * 16), g_xh + g);
        }
        // B: 64 k-rows x 32 chunks of 16B = 2048 chunks, 4/thread
#pragma unroll
        for (int i = 0; i < 4; i++) {
            int ch = tid + i * 512;
            int k = ch >> 5, c = ch & 31;
            size_t g = (size_t)(kt * 64 + k) * DDIM + cta_n + c * 8;
            cpa16(st + ST_B_OFF + k * 512 + ((c ^ (k & 7)) * 16), g_wh + g);
        }
    };

    float c[2][8][4];
#pragma unroll
    for (int i = 0; i < 2; i++)
#pragma unroll
        for (int j = 0; j < 8; j++)
#pragma unroll
            for (int q = 0; q < 4; q++) c[i][j][q] = 0.0f;

    load_st(0, 0); cp_commit();
    load_st(1, 1); cp_commit();
    load_st(2, 2); cp_commit();

    for (int kt = 0; kt < 16; kt++) {
        if (kt < 14)       cp_wait2();
        else if (kt == 14) cp_wait1();
        else               cp_wait0();
        __syncthreads();
        if (kt + 3 < 16) {
            load_st(kt + 3, (kt + 3) & 3);
            cp_commit();
        }

        uint32_t st = sb + (kt & 3) * STAGE_BYTES;
#pragma unroll
        for (int kk = 0; kk < 4; kk++) {
            uint32_t a[2][4], b[4][4];
#pragma unroll
            for (int mt = 0; mt < 2; mt++) {
                int row = warp_m * 32 + mt * 16 + (lane & 15);
                int ch  = kk * 2 + (lane >> 4);
                ldsm4(a[mt], st + row * 128 + ((ch ^ (row & 7)) * 16));
            }
#pragma unroll
            for (int nt = 0; nt < 4; nt++) {
                int k  = kk * 16 + (lane & 15);
                int nc = warp_n * 8 + nt * 2 + (lane >> 4);
                ldsm4t(b[nt], st + ST_B_OFF + k * 512 + ((nc ^ (k & 7)) * 16));
            }
#pragma unroll
            for (int mt = 0; mt < 2; mt++)
#pragma unroll
                for (int nj = 0; nj < 8; nj++)
                    mma16816(c[mt][nj], a[mt], &b[nj >> 1][(nj & 1) * 2]);
        }
    }

    // Epilogue: direct f32 stores from fragments
#pragma unroll
    for (int mt = 0; mt < 2; mt++) {
#pragma unroll
        for (int nj = 0; nj < 8; nj++) {
            int row = cta_m + warp_m * 32 + mt * 16 + (lane >> 2);
            int col = cta_n + warp_n * 64 + nj * 8 + (lane & 3) * 2;
            *reinterpret_cast<float2*>(&out[(size_t)row * DDIM + col]) =
                make_float2(c[mt][nj][0], c[mt][nj][1]);
            *reinterpret_cast<float2*>(&out[(size_t)(row + 8) * DDIM + col]) =
                make_float2(c[mt][nj][2], c[mt][nj][3]);
        }
    }
}

// ------------------------- launch -------------------------
extern "C" void kernel_launch(void* const* d_in, const int* in_sizes, int n_in,
                              void* d_out, int out_size) {
    const float* x = (const float*)d_in[0];                 // [8192,1024]
    const float* kern = (const float*)d_in[1];              // [3,1024,1024]
    const float* wv = kern + 2L * DDIM * DDIM;              // kernel[2]: [K,N]
    float* out = (float*)d_out;

    const int nx4 = BROWS * DDIM / 4;   // 2,097,152 (= 2048 blocks * 1024)
    const int nw4 = DDIM * DDIM / 4;    // 262,144   (= 256 blocks * 1024)
    cvt_kernel<<<(nx4 + nw4) / 1024, 256>>>((const float4*)x, (const float4*)wv, nx4);

    cudaFuncSetAttribute(gemm_fp16_kernel,
                         cudaFuncAttributeMaxDynamicSharedMemorySize, GEMM_SMEM);
    dim3 grid(DDIM / 256, BROWS / 128);  // (4, 64) = 256 CTAs
    gemm_fp16_kernel<<<grid, 512, GEMM_SMEM>>>(out);
}